// round 1
// baseline (speedup 1.0000x reference)
#include <cuda_runtime.h>
#include <cuda_bf16.h>
#include <cstddef>

// Problem constants
#define BB 2
#define TT 2048
#define DD 2048
#define HQ 16
#define HKV 8
#define HD 128
#define MROWS (BB*TT)   // 4096

// ---------------- scratch (static device globals; no cudaMalloc allowed) ----
__device__ float g_Qraw[(size_t)MROWS * (HQ*HD)];        // [B*T, 2048]
__device__ float g_Kraw[(size_t)MROWS * (HKV*HD)];       // [B*T, 1024]
__device__ float g_Vraw[(size_t)MROWS * (HKV*HD)];       // [B*T, 1024]
__device__ float g_Qn [(size_t)BB*HQ*TT*HD];             // [B,HQ,T,HD]
__device__ float g_Kn [(size_t)BB*HKV*TT*HD];            // [B,HKV,T,HD]
__device__ float g_S  [(size_t)BB*HQ*TT*TT];             // [B*HQ, T, T] (512MB, reused as P)
__device__ float g_ctx[(size_t)MROWS * (HQ*HD)];         // [B*T, 2048]

// ---------------- generic TN SGEMM: C[M,N] = A[M,K] * B[N,K]^T --------------
// 128x128 tile, BK=8, 256 threads, 8x8 per thread
__global__ __launch_bounds__(256) void sgemm_tn_128(
    const float* __restrict__ A, const float* __restrict__ B,
    float* __restrict__ C, int M, int N, int K)
{
    __shared__ float As[8][128];
    __shared__ float Bs[8][128];
    const int tid = threadIdx.x;
    const int tx = tid & 15, ty = tid >> 4;
    const int row0 = blockIdx.y * 128, col0 = blockIdx.x * 128;

    const int lr = tid >> 1;          // 0..127
    const int lc = (tid & 1) << 2;    // 0 or 4
    const float* Ap = A + (size_t)(row0 + lr) * K + lc;
    const float* Bp = B + (size_t)(col0 + lr) * K + lc;

    float acc[8][8] = {};
    for (int k0 = 0; k0 < K; k0 += 8) {
        float4 a = *(const float4*)(Ap + k0);
        float4 b = *(const float4*)(Bp + k0);
        As[lc+0][lr]=a.x; As[lc+1][lr]=a.y; As[lc+2][lr]=a.z; As[lc+3][lr]=a.w;
        Bs[lc+0][lr]=b.x; Bs[lc+1][lr]=b.y; Bs[lc+2][lr]=b.z; Bs[lc+3][lr]=b.w;
        __syncthreads();
#pragma unroll
        for (int kk = 0; kk < 8; kk++) {
            float ar[8], br[8];
            *(float4*)&ar[0] = *(const float4*)&As[kk][ty*8];
            *(float4*)&ar[4] = *(const float4*)&As[kk][ty*8+4];
            *(float4*)&br[0] = *(const float4*)&Bs[kk][tx*8];
            *(float4*)&br[4] = *(const float4*)&Bs[kk][tx*8+4];
#pragma unroll
            for (int i = 0; i < 8; i++)
#pragma unroll
                for (int j = 0; j < 8; j++)
                    acc[i][j] += ar[i]*br[j];
        }
        __syncthreads();
    }
#pragma unroll
    for (int i = 0; i < 8; i++) {
        float* Cp = C + (size_t)(row0 + ty*8 + i)*N + col0 + tx*8;
        *(float4*)Cp     = make_float4(acc[i][0],acc[i][1],acc[i][2],acc[i][3]);
        *(float4*)(Cp+4) = make_float4(acc[i][4],acc[i][5],acc[i][6],acc[i][7]);
    }
}

// ---------------- RMSNorm + RoPE + head-transpose --------------------------
// raw: [B*T, H*HD]; out: [B, H, T, HD]. One block (128 thr) per (bt, h).
__global__ __launch_bounds__(128) void norm_rope_kernel(
    const float* __restrict__ raw, float* __restrict__ out,
    const float* __restrict__ scale,
    const float* __restrict__ cosT, const float* __restrict__ sinT, int H)
{
    const int blk = blockIdx.x;
    const int h  = blk % H;
    const int bt = blk / H;
    const int t  = bt & (TT-1);
    const int b  = bt >> 11;           // bt / 2048
    const int d  = threadIdx.x;

    __shared__ float red[HD];
    float v = raw[(size_t)bt * (H*HD) + h*HD + d];
    red[d] = v*v;
    __syncthreads();
#pragma unroll
    for (int s = 64; s > 0; s >>= 1) {
        if (d < s) red[d] += red[d+s];
        __syncthreads();
    }
    float inv = rsqrtf(red[0]*(1.0f/HD) + 1e-6f);
    __syncthreads();
    float xn = v * inv * scale[d];
    red[d] = xn;
    __syncthreads();
    float rot = (d < 64) ? -red[d+64] : red[d-64];
    float o = xn * cosT[t*HD + d] + rot * sinT[t*HD + d];
    out[(((size_t)(b*H + h))*TT + t)*HD + d] = o;
}

// ---------------- causal scores: S = Q K^T / sqrt(HD) ----------------------
// grid (T/64 k-tiles, T/64 q-tiles, B*HQ); skips tiles above diagonal.
__global__ __launch_bounds__(256) void scores_kernel(
    const float* __restrict__ Q, const float* __restrict__ Kt,
    float* __restrict__ S)
{
    const int kb = blockIdx.x, qb = blockIdx.y;
    if (kb > qb) return;
    const int bh = blockIdx.z;
    const int b = bh >> 4, h = bh & 15;
    const int kv = h >> 1;             // GROUP = 2
    const int q0 = qb*64, k0 = kb*64;

    __shared__ float Qs[32][64];
    __shared__ float Ks[32][64];
    const int tid = threadIdx.x;
    const int tx = tid & 15, ty = tid >> 4;
    const float* Qbase = Q  + ((size_t)(b*HQ  + h )*TT + q0)*HD;
    const float* Kbase = Kt + ((size_t)(b*HKV + kv)*TT + k0)*HD;

    float acc[4][4] = {};
    for (int kc = 0; kc < HD; kc += 32) {
#pragma unroll
        for (int it = 0; it < 2; it++) {
            int r = (tid >> 3) + it*32;      // 0..63
            int c = (tid & 7) << 2;          // 0..28
            float4 a = *(const float4*)(Qbase + (size_t)r*HD + kc + c);
            Qs[c+0][r]=a.x; Qs[c+1][r]=a.y; Qs[c+2][r]=a.z; Qs[c+3][r]=a.w;
            float4 kb4 = *(const float4*)(Kbase + (size_t)r*HD + kc + c);
            Ks[c+0][r]=kb4.x; Ks[c+1][r]=kb4.y; Ks[c+2][r]=kb4.z; Ks[c+3][r]=kb4.w;
        }
        __syncthreads();
#pragma unroll
        for (int kk = 0; kk < 32; kk++) {
            float a[4], bv[4];
            *(float4*)a  = *(const float4*)&Qs[kk][ty*4];
            *(float4*)bv = *(const float4*)&Ks[kk][tx*4];
#pragma unroll
            for (int i = 0; i < 4; i++)
#pragma unroll
                for (int j = 0; j < 4; j++)
                    acc[i][j] += a[i]*bv[j];
        }
        __syncthreads();
    }
    const float sc = 0.08838834764831845f;   // 1/sqrt(128)
    float* Sb = S + ((size_t)bh*TT + q0)*TT + k0;
#pragma unroll
    for (int i = 0; i < 4; i++) {
        int q = q0 + ty*4 + i;
#pragma unroll
        for (int j = 0; j < 4; j++) {
            int k = k0 + tx*4 + j;
            float v = acc[i][j]*sc;
            if (k > q) v = -1e30f;
            Sb[(size_t)(ty*4+i)*TT + tx*4 + j] = v;
        }
    }
}

// ---------------- row softmax over valid causal prefix ---------------------
// One block (256 thr) per row (b,h,q). Processes n = ceil((q+1)/64)*64 cols.
__global__ __launch_bounds__(256) void softmax_kernel(float* __restrict__ S)
{
    const int q = blockIdx.x & (TT-1);
    float* Sr = S + (size_t)blockIdx.x * TT;
    const int n = ((q >> 6) + 1) << 6;
    const int tid = threadIdx.x;

    float vals[8];
    float m = -1e30f;
#pragma unroll
    for (int i = 0; i < 8; i++) {
        int idx = tid + (i << 8);
        vals[i] = (idx < n) ? Sr[idx] : -1e30f;
        m = fmaxf(m, vals[i]);
    }
    __shared__ float red[256];
    red[tid] = m; __syncthreads();
#pragma unroll
    for (int s = 128; s > 0; s >>= 1) {
        if (tid < s) red[tid] = fmaxf(red[tid], red[tid+s]);
        __syncthreads();
    }
    m = red[0]; __syncthreads();

    float sum = 0.f;
#pragma unroll
    for (int i = 0; i < 8; i++) { vals[i] = __expf(vals[i] - m); sum += vals[i]; }
    red[tid] = sum; __syncthreads();
#pragma unroll
    for (int s = 128; s > 0; s >>= 1) {
        if (tid < s) red[tid] += red[tid+s];
        __syncthreads();
    }
    float invs = 1.0f / red[0];
#pragma unroll
    for (int i = 0; i < 8; i++) {
        int idx = tid + (i << 8);
        if (idx < n) Sr[idx] = vals[i] * invs;
    }
}

// ---------------- ctx = P @ V (causal k-tiles only) ------------------------
// grid (T/64 q-tiles, 2 d-halves, B*HQ), 256 threads, 4x4 per thread.
// Writes ctx in [B*T, HQ*HD] layout directly.
__global__ __launch_bounds__(256) void pv_kernel(
    const float* __restrict__ P, const float* __restrict__ Vraw,
    float* __restrict__ ctx)
{
    const int qb = blockIdx.x;
    const int d0 = blockIdx.y * 64;
    const int bh = blockIdx.z;
    const int b = bh >> 4, h = bh & 15, kv = h >> 1;
    const int q0 = qb * 64;

    __shared__ float Ps[64][65];
    __shared__ float Vs[64][64];
    const int tid = threadIdx.x;
    const int tx = tid & 15, ty = tid >> 4;

    float acc[4][4] = {};
    const float* Pb = P + ((size_t)bh*TT + q0)*TT;
    const float* Vb = Vraw + (size_t)b*TT*(HKV*HD) + kv*HD + d0;

    const int nkt = qb + 1;
    for (int kt = 0; kt < nkt; kt++) {
        const int k0 = kt*64;
#pragma unroll
        for (int it = 0; it < 4; it++) {
            int r = (tid >> 4) + it*16;      // 0..63
            int c = (tid & 15) << 2;         // 0..60
            float4 p = *(const float4*)(Pb + (size_t)r*TT + k0 + c);
            Ps[r][c]=p.x; Ps[r][c+1]=p.y; Ps[r][c+2]=p.z; Ps[r][c+3]=p.w;
            float4 v = *(const float4*)(Vb + (size_t)(k0 + r)*(HKV*HD) + c);
            Vs[r][c]=v.x; Vs[r][c+1]=v.y; Vs[r][c+2]=v.z; Vs[r][c+3]=v.w;
        }
        __syncthreads();
#pragma unroll
        for (int kk = 0; kk < 64; kk++) {
            float pr[4], vr[4];
#pragma unroll
            for (int i = 0; i < 4; i++) pr[i] = Ps[ty*4+i][kk];
            *(float4*)vr = *(const float4*)&Vs[kk][tx*4];
#pragma unroll
            for (int i = 0; i < 4; i++)
#pragma unroll
                for (int j = 0; j < 4; j++)
                    acc[i][j] += pr[i]*vr[j];
        }
        __syncthreads();
    }
#pragma unroll
    for (int i = 0; i < 4; i++) {
        float* cp = ctx + ((size_t)(b*TT + q0 + ty*4 + i))*(HQ*HD) + h*HD + d0 + tx*4;
        *(float4*)cp = make_float4(acc[i][0],acc[i][1],acc[i][2],acc[i][3]);
    }
}

// ---------------- launch ----------------------------------------------------
extern "C" void kernel_launch(void* const* d_in, const int* in_sizes, int n_in,
                              void* d_out, int out_size)
{
    const float* x       = (const float*)d_in[0];
    // d_in[1] = mask (causal, handled analytically)
    const float* cosT    = (const float*)d_in[2];
    const float* sinT    = (const float*)d_in[3];
    const float* Wq      = (const float*)d_in[4];
    const float* Wk      = (const float*)d_in[5];
    const float* Wv      = (const float*)d_in[6];
    const float* Wo      = (const float*)d_in[7];
    const float* q_scale = (const float*)d_in[8];
    const float* k_scale = (const float*)d_in[9];
    float* out = (float*)d_out;

    float *Qraw, *Kraw, *Vraw, *Qn, *Kn, *S, *ctx;
    cudaGetSymbolAddress((void**)&Qraw, g_Qraw);
    cudaGetSymbolAddress((void**)&Kraw, g_Kraw);
    cudaGetSymbolAddress((void**)&Vraw, g_Vraw);
    cudaGetSymbolAddress((void**)&Qn,   g_Qn);
    cudaGetSymbolAddress((void**)&Kn,   g_Kn);
    cudaGetSymbolAddress((void**)&S,    g_S);
    cudaGetSymbolAddress((void**)&ctx,  g_ctx);

    // 1-3: QKV projections (C = A * W^T)
    sgemm_tn_128<<<dim3(HQ*HD/128,  MROWS/128), 256>>>(x, Wq, Qraw, MROWS, HQ*HD,  DD);
    sgemm_tn_128<<<dim3(HKV*HD/128, MROWS/128), 256>>>(x, Wk, Kraw, MROWS, HKV*HD, DD);
    sgemm_tn_128<<<dim3(HKV*HD/128, MROWS/128), 256>>>(x, Wv, Vraw, MROWS, HKV*HD, DD);

    // 4-5: RMSNorm + RoPE + transpose to [B,H,T,HD]
    norm_rope_kernel<<<MROWS*HQ,  128>>>(Qraw, Qn, q_scale, cosT, sinT, HQ);
    norm_rope_kernel<<<MROWS*HKV, 128>>>(Kraw, Kn, k_scale, cosT, sinT, HKV);

    // 6: causal scores
    scores_kernel<<<dim3(TT/64, TT/64, BB*HQ), 256>>>(Qn, Kn, S);

    // 7: row softmax
    softmax_kernel<<<BB*HQ*TT, 256>>>(S);

    // 8: ctx = P @ V (V read straight from Vraw, GQA-mapped)
    pv_kernel<<<dim3(TT/64, 2, BB*HQ), 256>>>(S, Vraw, ctx);

    // 9: output projection
    sgemm_tn_128<<<dim3(DD/128, MROWS/128), 256>>>(ctx, Wo, out, MROWS, DD, DD);
}

// round 2
// speedup vs baseline: 1.8059x; 1.8059x over previous
#include <cuda_runtime.h>
#include <cuda_bf16.h>
#include <cstdint>
#include <cstddef>

// Problem constants
#define BB 2
#define TT 2048
#define DD 2048
#define HQ 16
#define HKV 8
#define HD 128
#define MROWS (BB*TT)   // 4096

typedef __nv_bfloat16 bf16;

// ---------------- scratch (static device globals; no cudaMalloc allowed) ----
__device__ float g_Qraw[(size_t)MROWS * (HQ*HD)];
__device__ float g_Kraw[(size_t)MROWS * (HKV*HD)];
__device__ float g_Vraw[(size_t)MROWS * (HKV*HD)];
__device__ float g_Qn [(size_t)BB*HQ*TT*HD];
__device__ float g_Kn [(size_t)BB*HKV*TT*HD];
__device__ float g_S  [(size_t)BB*HQ*TT*TT];          // 512MB, reused as P

__device__ bf16 g_xh [(size_t)MROWS*DD],    g_xl [(size_t)MROWS*DD];
__device__ bf16 g_Wqh[(size_t)HQ*HD*DD],    g_Wql[(size_t)HQ*HD*DD];
__device__ bf16 g_Wkh[(size_t)HKV*HD*DD],   g_Wkl[(size_t)HKV*HD*DD];
__device__ bf16 g_Wvh[(size_t)HKV*HD*DD],   g_Wvl[(size_t)HKV*HD*DD];
__device__ bf16 g_Woh[(size_t)DD*HQ*HD],    g_Wol[(size_t)DD*HQ*HD];
__device__ bf16 g_ctxh[(size_t)MROWS*HQ*HD], g_ctxl[(size_t)MROWS*HQ*HD];

// ---------------- PTX helpers ------------------------------------------------
__device__ __forceinline__ void ldsm4(uint32_t* r, uint32_t a) {
    asm volatile("ldmatrix.sync.aligned.m8n8.x4.shared.b16 {%0,%1,%2,%3}, [%4];\n"
        : "=r"(r[0]), "=r"(r[1]), "=r"(r[2]), "=r"(r[3]) : "r"(a));
}
__device__ __forceinline__ void mma16816(float* c, const uint32_t* a, const uint32_t* b) {
    asm volatile("mma.sync.aligned.m16n8k16.row.col.f32.bf16.bf16.f32 "
        "{%0,%1,%2,%3}, {%4,%5,%6,%7}, {%8,%9}, {%0,%1,%2,%3};\n"
        : "+f"(c[0]), "+f"(c[1]), "+f"(c[2]), "+f"(c[3])
        : "r"(a[0]), "r"(a[1]), "r"(a[2]), "r"(a[3]), "r"(b[0]), "r"(b[1]));
}
__device__ __forceinline__ void cp_async16(uint32_t dst, const void* src) {
    asm volatile("cp.async.ca.shared.global [%0], [%1], 16;\n" :: "r"(dst), "l"(src));
}
__device__ __forceinline__ void cp_commit() {
    asm volatile("cp.async.commit_group;\n" ::: "memory");
}

// ---------------- fp32 -> bf16 hi/lo split ----------------------------------
__global__ __launch_bounds__(256) void split_kernel(
    const float4* __restrict__ in, bf16* __restrict__ hi, bf16* __restrict__ lo, int n4)
{
    int i = blockIdx.x * 256 + threadIdx.x;
    if (i >= n4) return;
    float4 v = in[i];
    bf16 h0 = __float2bfloat16(v.x), h1 = __float2bfloat16(v.y);
    bf16 h2 = __float2bfloat16(v.z), h3 = __float2bfloat16(v.w);
    bf16 l0 = __float2bfloat16(v.x - __bfloat162float(h0));
    bf16 l1 = __float2bfloat16(v.y - __bfloat162float(h1));
    bf16 l2 = __float2bfloat16(v.z - __bfloat162float(h2));
    bf16 l3 = __float2bfloat16(v.w - __bfloat162float(h3));
    __nv_bfloat162* H = (__nv_bfloat162*)(hi + (size_t)i*4);
    __nv_bfloat162* L = (__nv_bfloat162*)(lo + (size_t)i*4);
    H[0] = __halves2bfloat162(h0, h1); H[1] = __halves2bfloat162(h2, h3);
    L[0] = __halves2bfloat162(l0, l1); L[1] = __halves2bfloat162(l2, l3);
}

// ---------------- tensor-core GEMM: C[M,N] = A[M,K]*B[N,K]^T (bf16x3) -------
// 128x128 block tile, BK=32, 256 threads (8 warps, 32x64 warp tile),
// cp.async double-buffered.
#define BKC 32
#define PAD 40
#define ARR (128*PAD)          // bf16 elems per array per stage
#define STG (4*ARR)            // bf16 elems per stage

__global__ __launch_bounds__(256) void gemm_bf16x3(
    const bf16* __restrict__ Ah, const bf16* __restrict__ Al,
    const bf16* __restrict__ Bh, const bf16* __restrict__ Bl,
    float* __restrict__ C, int M, int N, int K)
{
    extern __shared__ bf16 sm[];
    const int tid  = threadIdx.x;
    const int lane = tid & 31, wid = tid >> 5;
    const int row0 = blockIdx.y * 128, col0 = blockIdx.x * 128;
    const uint32_t sbase = (uint32_t)__cvta_generic_to_shared(sm);

    const int wm = (wid >> 1) * 32;     // 0,32,64,96
    const int wn = (wid & 1) * 64;      // 0,64

    // global load coords: each thread 2 chunks (16B) per array
    const int m0 = tid >> 2;            // 0..63
    const int c0 = (tid & 3) * 8;       // 0,8,16,24

    // ldmatrix per-lane offsets
    const int r   = lane & 7, blk = lane >> 3;
    const int a_row = ((blk & 1) << 3) + r;
    const int a_col = (blk >> 1) << 3;
    const int b_row = ((blk >> 1) << 3) + r;
    const int b_col = (blk & 1) << 3;

    float acc[2][8][4];
#pragma unroll
    for (int i = 0; i < 2; i++)
#pragma unroll
        for (int j = 0; j < 8; j++)
#pragma unroll
            for (int k = 0; k < 4; k++) acc[i][j][k] = 0.f;

    const int niter = K / BKC;
    const bf16* gA[2] = {Ah, Al};
    const bf16* gB[2] = {Bh, Bl};

    // stage issue: A arrays use row0, B arrays use col0
#define ISSUE(it, stage) do {                                                   \
    const int k0_ = (it) * BKC;                                                 \
    uint32_t sst_ = sbase + (uint32_t)(stage) * (STG * 2);                      \
    _Pragma("unroll")                                                           \
    for (int arr_ = 0; arr_ < 2; arr_++) {                                      \
        _Pragma("unroll")                                                       \
        for (int hh_ = 0; hh_ < 2; hh_++) {                                     \
            int m_ = m0 + hh_ * 64;                                             \
            cp_async16(sst_ + (uint32_t)((arr_*ARR + m_*PAD + c0) * 2),         \
                       gA[arr_] + (size_t)(row0 + m_) * K + k0_ + c0);          \
            cp_async16(sst_ + (uint32_t)(((2+arr_)*ARR + m_*PAD + c0) * 2),     \
                       gB[arr_] + (size_t)(col0 + m_) * K + k0_ + c0);          \
        }                                                                       \
    }                                                                           \
} while (0)

    ISSUE(0, 0);
    cp_commit();

    for (int it = 0; it < niter; it++) {
        if (it + 1 < niter) {
            ISSUE(it + 1, (it + 1) & 1);
            cp_commit();
            asm volatile("cp.async.wait_group 1;\n" ::: "memory");
        } else {
            asm volatile("cp.async.wait_group 0;\n" ::: "memory");
        }
        __syncthreads();

        const uint32_t sst = sbase + (uint32_t)(it & 1) * (STG * 2);
#pragma unroll
        for (int ks = 0; ks < 2; ks++) {
            const int kofs = ks * 16;
            uint32_t ah[2][4], al[2][4], bh[4][4], bl[4][4];
#pragma unroll
            for (int mt = 0; mt < 2; mt++) {
                uint32_t addr = sst + (uint32_t)(((wm + mt*16 + a_row)*PAD + kofs + a_col) * 2);
                ldsm4(ah[mt], addr);
                ldsm4(al[mt], addr + ARR * 2);
            }
#pragma unroll
            for (int p = 0; p < 4; p++) {
                uint32_t addr = sst + (uint32_t)((2*ARR + (wn + p*16 + b_row)*PAD + kofs + b_col) * 2);
                ldsm4(bh[p], addr);
                ldsm4(bl[p], addr + ARR * 2);
            }
#pragma unroll
            for (int mt = 0; mt < 2; mt++)
#pragma unroll
                for (int p = 0; p < 4; p++) {
                    mma16816(acc[mt][2*p],   ah[mt], &bh[p][0]);
                    mma16816(acc[mt][2*p+1], ah[mt], &bh[p][2]);
                    mma16816(acc[mt][2*p],   ah[mt], &bl[p][0]);
                    mma16816(acc[mt][2*p+1], ah[mt], &bl[p][2]);
                    mma16816(acc[mt][2*p],   al[mt], &bh[p][0]);
                    mma16816(acc[mt][2*p+1], al[mt], &bh[p][2]);
                }
        }
        __syncthreads();
    }
#undef ISSUE

    const int gr = lane >> 2, gc = (lane & 3) * 2;
#pragma unroll
    for (int mt = 0; mt < 2; mt++)
#pragma unroll
        for (int nt = 0; nt < 8; nt++) {
            int row = row0 + wm + mt*16 + gr;
            int col = col0 + wn + nt*8 + gc;
            float2 v0 = make_float2(acc[mt][nt][0], acc[mt][nt][1]);
            float2 v1 = make_float2(acc[mt][nt][2], acc[mt][nt][3]);
            *(float2*)&C[(size_t)row*N + col]       = v0;
            *(float2*)&C[(size_t)(row+8)*N + col]   = v1;
        }
}

// ---------------- RMSNorm + RoPE + head-transpose ---------------------------
__global__ __launch_bounds__(128) void norm_rope_kernel(
    const float* __restrict__ raw, float* __restrict__ out,
    const float* __restrict__ scale,
    const float* __restrict__ cosT, const float* __restrict__ sinT, int H)
{
    const int blk = blockIdx.x;
    const int h  = blk % H;
    const int bt = blk / H;
    const int t  = bt & (TT-1);
    const int b  = bt >> 11;
    const int d  = threadIdx.x;

    __shared__ float red[HD];
    float v = raw[(size_t)bt * (H*HD) + h*HD + d];
    red[d] = v*v;
    __syncthreads();
#pragma unroll
    for (int s = 64; s > 0; s >>= 1) {
        if (d < s) red[d] += red[d+s];
        __syncthreads();
    }
    float inv = rsqrtf(red[0]*(1.0f/HD) + 1e-6f);
    __syncthreads();
    float xn = v * inv * scale[d];
    red[d] = xn;
    __syncthreads();
    float rot = (d < 64) ? -red[d+64] : red[d-64];
    float o = xn * cosT[t*HD + d] + rot * sinT[t*HD + d];
    out[(((size_t)(b*H + h))*TT + t)*HD + d] = o;
}

// ---------------- causal scores: S = Q K^T / sqrt(HD) ------------------------
__global__ __launch_bounds__(256) void scores_kernel(
    const float* __restrict__ Q, const float* __restrict__ Kt,
    float* __restrict__ S)
{
    const int kb = blockIdx.x, qb = blockIdx.y;
    if (kb > qb) return;
    const int bh = blockIdx.z;
    const int b = bh >> 4, h = bh & 15;
    const int kv = h >> 1;
    const int q0 = qb*64, k0 = kb*64;

    __shared__ float Qs[32][64];
    __shared__ float Ks[32][64];
    const int tid = threadIdx.x;
    const int tx = tid & 15, ty = tid >> 4;
    const float* Qbase = Q  + ((size_t)(b*HQ  + h )*TT + q0)*HD;
    const float* Kbase = Kt + ((size_t)(b*HKV + kv)*TT + k0)*HD;

    float acc[4][4] = {};
    for (int kc = 0; kc < HD; kc += 32) {
#pragma unroll
        for (int it = 0; it < 2; it++) {
            int rr = (tid >> 3) + it*32;
            int cc = (tid & 7) << 2;
            float4 a = *(const float4*)(Qbase + (size_t)rr*HD + kc + cc);
            Qs[cc+0][rr]=a.x; Qs[cc+1][rr]=a.y; Qs[cc+2][rr]=a.z; Qs[cc+3][rr]=a.w;
            float4 kb4 = *(const float4*)(Kbase + (size_t)rr*HD + kc + cc);
            Ks[cc+0][rr]=kb4.x; Ks[cc+1][rr]=kb4.y; Ks[cc+2][rr]=kb4.z; Ks[cc+3][rr]=kb4.w;
        }
        __syncthreads();
#pragma unroll
        for (int kk = 0; kk < 32; kk++) {
            float a[4], bv[4];
            *(float4*)a  = *(const float4*)&Qs[kk][ty*4];
            *(float4*)bv = *(const float4*)&Ks[kk][tx*4];
#pragma unroll
            for (int i = 0; i < 4; i++)
#pragma unroll
                for (int j = 0; j < 4; j++)
                    acc[i][j] += a[i]*bv[j];
        }
        __syncthreads();
    }
    const float sc = 0.08838834764831845f;
    float* Sb = S + ((size_t)bh*TT + q0)*TT + k0;
#pragma unroll
    for (int i = 0; i < 4; i++) {
        int q = q0 + ty*4 + i;
#pragma unroll
        for (int j = 0; j < 4; j++) {
            int k = k0 + tx*4 + j;
            float v = acc[i][j]*sc;
            if (k > q) v = -1e30f;
            Sb[(size_t)(ty*4+i)*TT + tx*4 + j] = v;
        }
    }
}

// ---------------- row softmax over valid causal prefix -----------------------
__global__ __launch_bounds__(256) void softmax_kernel(float* __restrict__ S)
{
    const int q = blockIdx.x & (TT-1);
    float* Sr = S + (size_t)blockIdx.x * TT;
    const int n = ((q >> 6) + 1) << 6;
    const int tid = threadIdx.x;

    float vals[8];
    float m = -1e30f;
#pragma unroll
    for (int i = 0; i < 8; i++) {
        int idx = tid + (i << 8);
        vals[i] = (idx < n) ? Sr[idx] : -1e30f;
        m = fmaxf(m, vals[i]);
    }
    __shared__ float red[256];
    red[tid] = m; __syncthreads();
#pragma unroll
    for (int s = 128; s > 0; s >>= 1) {
        if (tid < s) red[tid] = fmaxf(red[tid], red[tid+s]);
        __syncthreads();
    }
    m = red[0]; __syncthreads();

    float sum = 0.f;
#pragma unroll
    for (int i = 0; i < 8; i++) { vals[i] = __expf(vals[i] - m); sum += vals[i]; }
    red[tid] = sum; __syncthreads();
#pragma unroll
    for (int s = 128; s > 0; s >>= 1) {
        if (tid < s) red[tid] += red[tid+s];
        __syncthreads();
    }
    float invs = 1.0f / red[0];
#pragma unroll
    for (int i = 0; i < 8; i++) {
        int idx = tid + (i << 8);
        if (idx < n) Sr[idx] = vals[i] * invs;
    }
}

// ---------------- ctx = P @ V; writes bf16 hi/lo splits ----------------------
__global__ __launch_bounds__(256) void pv_kernel(
    const float* __restrict__ P, const float* __restrict__ Vraw,
    bf16* __restrict__ ctxh, bf16* __restrict__ ctxl)
{
    const int qb = blockIdx.x;
    const int d0 = blockIdx.y * 64;
    const int bh = blockIdx.z;
    const int b = bh >> 4, hh = bh & 15, kv = hh >> 1;
    const int q0 = qb * 64;

    __shared__ float Ps[64][65];
    __shared__ float Vs[64][64];
    const int tid = threadIdx.x;
    const int tx = tid & 15, ty = tid >> 4;

    float acc[4][4] = {};
    const float* Pb = P + ((size_t)bh*TT + q0)*TT;
    const float* Vb = Vraw + (size_t)b*TT*(HKV*HD) + kv*HD + d0;

    const int nkt = qb + 1;
    for (int kt = 0; kt < nkt; kt++) {
        const int k0 = kt*64;
#pragma unroll
        for (int it = 0; it < 4; it++) {
            int rr = (tid >> 4) + it*16;
            int cc = (tid & 15) << 2;
            float4 p = *(const float4*)(Pb + (size_t)rr*TT + k0 + cc);
            Ps[rr][cc]=p.x; Ps[rr][cc+1]=p.y; Ps[rr][cc+2]=p.z; Ps[rr][cc+3]=p.w;
            float4 v = *(const float4*)(Vb + (size_t)(k0 + rr)*(HKV*HD) + cc);
            Vs[rr][cc]=v.x; Vs[rr][cc+1]=v.y; Vs[rr][cc+2]=v.z; Vs[rr][cc+3]=v.w;
        }
        __syncthreads();
#pragma unroll
        for (int kk = 0; kk < 64; kk++) {
            float pr[4], vr[4];
#pragma unroll
            for (int i = 0; i < 4; i++) pr[i] = Ps[ty*4+i][kk];
            *(float4*)vr = *(const float4*)&Vs[kk][tx*4];
#pragma unroll
            for (int i = 0; i < 4; i++)
#pragma unroll
                for (int j = 0; j < 4; j++)
                    acc[i][j] += pr[i]*vr[j];
        }
        __syncthreads();
    }
#pragma unroll
    for (int i = 0; i < 4; i++) {
        size_t off = ((size_t)(b*TT + q0 + ty*4 + i))*(HQ*HD) + hh*HD + d0 + tx*4;
        bf16 h0 = __float2bfloat16(acc[i][0]);
        bf16 h1 = __float2bfloat16(acc[i][1]);
        bf16 h2 = __float2bfloat16(acc[i][2]);
        bf16 h3 = __float2bfloat16(acc[i][3]);
        bf16 l0 = __float2bfloat16(acc[i][0] - __bfloat162float(h0));
        bf16 l1 = __float2bfloat16(acc[i][1] - __bfloat162float(h1));
        bf16 l2 = __float2bfloat16(acc[i][2] - __bfloat162float(h2));
        bf16 l3 = __float2bfloat16(acc[i][3] - __bfloat162float(h3));
        __nv_bfloat162* H = (__nv_bfloat162*)(ctxh + off);
        __nv_bfloat162* L = (__nv_bfloat162*)(ctxl + off);
        H[0] = __halves2bfloat162(h0, h1); H[1] = __halves2bfloat162(h2, h3);
        L[0] = __halves2bfloat162(l0, l1); L[1] = __halves2bfloat162(l2, l3);
    }
}

// ---------------- launch ------------------------------------------------------
extern "C" void kernel_launch(void* const* d_in, const int* in_sizes, int n_in,
                              void* d_out, int out_size)
{
    const float* x       = (const float*)d_in[0];
    const float* cosT    = (const float*)d_in[2];
    const float* sinT    = (const float*)d_in[3];
    const float* Wq      = (const float*)d_in[4];
    const float* Wk      = (const float*)d_in[5];
    const float* Wv      = (const float*)d_in[6];
    const float* Wo      = (const float*)d_in[7];
    const float* q_scale = (const float*)d_in[8];
    const float* k_scale = (const float*)d_in[9];
    float* out = (float*)d_out;

    float *Qraw, *Kraw, *Vraw, *Qn, *Kn, *S;
    bf16 *xh,*xl,*Wqh,*Wql,*Wkh,*Wkl,*Wvh,*Wvl,*Woh,*Wol,*ctxh,*ctxl;
    cudaGetSymbolAddress((void**)&Qraw, g_Qraw);
    cudaGetSymbolAddress((void**)&Kraw, g_Kraw);
    cudaGetSymbolAddress((void**)&Vraw, g_Vraw);
    cudaGetSymbolAddress((void**)&Qn,   g_Qn);
    cudaGetSymbolAddress((void**)&Kn,   g_Kn);
    cudaGetSymbolAddress((void**)&S,    g_S);
    cudaGetSymbolAddress((void**)&xh,   g_xh);   cudaGetSymbolAddress((void**)&xl,   g_xl);
    cudaGetSymbolAddress((void**)&Wqh,  g_Wqh);  cudaGetSymbolAddress((void**)&Wql,  g_Wql);
    cudaGetSymbolAddress((void**)&Wkh,  g_Wkh);  cudaGetSymbolAddress((void**)&Wkl,  g_Wkl);
    cudaGetSymbolAddress((void**)&Wvh,  g_Wvh);  cudaGetSymbolAddress((void**)&Wvl,  g_Wvl);
    cudaGetSymbolAddress((void**)&Woh,  g_Woh);  cudaGetSymbolAddress((void**)&Wol,  g_Wol);
    cudaGetSymbolAddress((void**)&ctxh, g_ctxh); cudaGetSymbolAddress((void**)&ctxl, g_ctxl);

    static bool attr_set = false;
    if (!attr_set) {
        cudaFuncSetAttribute(gemm_bf16x3, cudaFuncAttributeMaxDynamicSharedMemorySize, 2*STG*2);
        attr_set = true;
    }
    const int smem = 2*STG*2;   // 2 stages * STG bf16 * 2B = 81920

    // 0: split inputs to bf16 hi/lo
    split_kernel<<<(MROWS*DD/4 + 255)/256, 256>>>((const float4*)x,  xh,  xl,  MROWS*DD/4);
    split_kernel<<<(HQ*HD*DD/4 + 255)/256, 256>>>((const float4*)Wq, Wqh, Wql, HQ*HD*DD/4);
    split_kernel<<<(HKV*HD*DD/4 + 255)/256, 256>>>((const float4*)Wk, Wkh, Wkl, HKV*HD*DD/4);
    split_kernel<<<(HKV*HD*DD/4 + 255)/256, 256>>>((const float4*)Wv, Wvh, Wvl, HKV*HD*DD/4);
    split_kernel<<<(DD*HQ*HD/4 + 255)/256, 256>>>((const float4*)Wo, Woh, Wol, DD*HQ*HD/4);

    // 1-3: QKV projections on tensor cores
    gemm_bf16x3<<<dim3((HQ*HD)/128,  MROWS/128), 256, smem>>>(xh, xl, Wqh, Wql, Qraw, MROWS, HQ*HD,  DD);
    gemm_bf16x3<<<dim3((HKV*HD)/128, MROWS/128), 256, smem>>>(xh, xl, Wkh, Wkl, Kraw, MROWS, HKV*HD, DD);
    gemm_bf16x3<<<dim3((HKV*HD)/128, MROWS/128), 256, smem>>>(xh, xl, Wvh, Wvl, Vraw, MROWS, HKV*HD, DD);

    // 4-5: RMSNorm + RoPE + transpose
    norm_rope_kernel<<<MROWS*HQ,  128>>>(Qraw, Qn, q_scale, cosT, sinT, HQ);
    norm_rope_kernel<<<MROWS*HKV, 128>>>(Kraw, Kn, k_scale, cosT, sinT, HKV);

    // 6: causal scores
    scores_kernel<<<dim3(TT/64, TT/64, BB*HQ), 256>>>(Qn, Kn, S);

    // 7: row softmax
    softmax_kernel<<<BB*HQ*TT, 256>>>(S);

    // 8: ctx = P @ V (emits bf16 hi/lo)
    pv_kernel<<<dim3(TT/64, 2, BB*HQ), 256>>>(S, Vraw, ctxh, ctxl);

    // 9: output projection on tensor cores
    gemm_bf16x3<<<dim3(DD/128, MROWS/128), 256, smem>>>(ctxh, ctxl, Woh, Wol, out, MROWS, DD, DD);
}

// round 3
// speedup vs baseline: 3.0905x; 1.7113x over previous
#include <cuda_runtime.h>
#include <cuda_bf16.h>
#include <cstdint>
#include <cstddef>

// Problem constants
#define BB 2
#define TT 2048
#define DD 2048
#define HQ 16
#define HKV 8
#define HD 128
#define MROWS (BB*TT)   // 4096

typedef __nv_bfloat16 bf16;

// log2(e)/sqrt(128)
#define QSCALE 0.12752551164384637f

// ---------------- scratch (static device globals) ---------------------------
__device__ float g_Qraw[(size_t)MROWS * (HQ*HD)];
__device__ float g_Kraw[(size_t)MROWS * (HKV*HD)];
__device__ float g_Vraw[(size_t)MROWS * (HKV*HD)];

__device__ bf16 g_xh [(size_t)MROWS*DD],    g_xl [(size_t)MROWS*DD];
__device__ bf16 g_Wqh[(size_t)HQ*HD*DD],    g_Wql[(size_t)HQ*HD*DD];
__device__ bf16 g_Wkh[(size_t)HKV*HD*DD],   g_Wkl[(size_t)HKV*HD*DD];
__device__ bf16 g_Wvh[(size_t)HKV*HD*DD],   g_Wvl[(size_t)HKV*HD*DD];
__device__ bf16 g_Woh[(size_t)DD*HQ*HD],    g_Wol[(size_t)DD*HQ*HD];
__device__ bf16 g_Qh [(size_t)BB*HQ*TT*HD],  g_Ql [(size_t)BB*HQ*TT*HD];
__device__ bf16 g_Kh [(size_t)BB*HKV*TT*HD], g_Kl [(size_t)BB*HKV*TT*HD];
__device__ bf16 g_Vh [(size_t)MROWS*HKV*HD], g_Vl [(size_t)MROWS*HKV*HD];
__device__ bf16 g_ctxh[(size_t)MROWS*HQ*HD], g_ctxl[(size_t)MROWS*HQ*HD];

// ---------------- PTX helpers ------------------------------------------------
__device__ __forceinline__ void ldsm4(uint32_t* r, uint32_t a) {
    asm volatile("ldmatrix.sync.aligned.m8n8.x4.shared.b16 {%0,%1,%2,%3}, [%4];\n"
        : "=r"(r[0]), "=r"(r[1]), "=r"(r[2]), "=r"(r[3]) : "r"(a));
}
__device__ __forceinline__ void ldsm4t(uint32_t* r, uint32_t a) {
    asm volatile("ldmatrix.sync.aligned.m8n8.x4.trans.shared.b16 {%0,%1,%2,%3}, [%4];\n"
        : "=r"(r[0]), "=r"(r[1]), "=r"(r[2]), "=r"(r[3]) : "r"(a));
}
__device__ __forceinline__ void mma16816(float* c, const uint32_t* a, const uint32_t* b) {
    asm volatile("mma.sync.aligned.m16n8k16.row.col.f32.bf16.bf16.f32 "
        "{%0,%1,%2,%3}, {%4,%5,%6,%7}, {%8,%9}, {%0,%1,%2,%3};\n"
        : "+f"(c[0]), "+f"(c[1]), "+f"(c[2]), "+f"(c[3])
        : "r"(a[0]), "r"(a[1]), "r"(a[2]), "r"(a[3]), "r"(b[0]), "r"(b[1]));
}
__device__ __forceinline__ void cp_async16(uint32_t dst, const void* src) {
    asm volatile("cp.async.ca.shared.global [%0], [%1], 16;\n" :: "r"(dst), "l"(src));
}
__device__ __forceinline__ void cp_commit() {
    asm volatile("cp.async.commit_group;\n" ::: "memory");
}
__device__ __forceinline__ uint32_t packbf(float a, float b) {
    __nv_bfloat162 t = __floats2bfloat162_rn(a, b);
    return *(uint32_t*)&t;
}

// ---------------- fp32 -> bf16 hi/lo split ----------------------------------
__global__ __launch_bounds__(256) void split_kernel(
    const float4* __restrict__ in, bf16* __restrict__ hi, bf16* __restrict__ lo, int n4)
{
    int i = blockIdx.x * 256 + threadIdx.x;
    if (i >= n4) return;
    float4 v = in[i];
    bf16 h0 = __float2bfloat16(v.x), h1 = __float2bfloat16(v.y);
    bf16 h2 = __float2bfloat16(v.z), h3 = __float2bfloat16(v.w);
    bf16 l0 = __float2bfloat16(v.x - __bfloat162float(h0));
    bf16 l1 = __float2bfloat16(v.y - __bfloat162float(h1));
    bf16 l2 = __float2bfloat16(v.z - __bfloat162float(h2));
    bf16 l3 = __float2bfloat16(v.w - __bfloat162float(h3));
    __nv_bfloat162* H = (__nv_bfloat162*)(hi + (size_t)i*4);
    __nv_bfloat162* L = (__nv_bfloat162*)(lo + (size_t)i*4);
    H[0] = __halves2bfloat162(h0, h1); H[1] = __halves2bfloat162(h2, h3);
    L[0] = __halves2bfloat162(l0, l1); L[1] = __halves2bfloat162(l2, l3);
}

// ---------------- tensor-core GEMM: C[M,N] = A[M,K]*B[N,K]^T (bf16x3) -------
#define BKC 32
#define PAD 40
#define ARR (128*PAD)
#define STG (4*ARR)

__global__ __launch_bounds__(256) void gemm_bf16x3(
    const bf16* __restrict__ Ah, const bf16* __restrict__ Al,
    const bf16* __restrict__ Bh, const bf16* __restrict__ Bl,
    float* __restrict__ C, int M, int N, int K)
{
    extern __shared__ bf16 sm[];
    const int tid  = threadIdx.x;
    const int lane = tid & 31, wid = tid >> 5;
    const int row0 = blockIdx.y * 128, col0 = blockIdx.x * 128;
    const uint32_t sbase = (uint32_t)__cvta_generic_to_shared(sm);

    const int wm = (wid >> 1) * 32;
    const int wn = (wid & 1) * 64;
    const int m0 = tid >> 2;
    const int c0 = (tid & 3) * 8;

    const int r   = lane & 7, blk = lane >> 3;
    const int a_row = ((blk & 1) << 3) + r;
    const int a_col = (blk >> 1) << 3;
    const int b_row = ((blk >> 1) << 3) + r;
    const int b_col = (blk & 1) << 3;

    float acc[2][8][4];
#pragma unroll
    for (int i = 0; i < 2; i++)
#pragma unroll
        for (int j = 0; j < 8; j++)
#pragma unroll
            for (int k = 0; k < 4; k++) acc[i][j][k] = 0.f;

    const int niter = K / BKC;
    const bf16* gA[2] = {Ah, Al};
    const bf16* gB[2] = {Bh, Bl};

#define ISSUE(it, stage) do {                                                   \
    const int k0_ = (it) * BKC;                                                 \
    uint32_t sst_ = sbase + (uint32_t)(stage) * (STG * 2);                      \
    _Pragma("unroll")                                                           \
    for (int arr_ = 0; arr_ < 2; arr_++) {                                      \
        _Pragma("unroll")                                                       \
        for (int hh_ = 0; hh_ < 2; hh_++) {                                     \
            int m_ = m0 + hh_ * 64;                                             \
            cp_async16(sst_ + (uint32_t)((arr_*ARR + m_*PAD + c0) * 2),         \
                       gA[arr_] + (size_t)(row0 + m_) * K + k0_ + c0);          \
            cp_async16(sst_ + (uint32_t)(((2+arr_)*ARR + m_*PAD + c0) * 2),     \
                       gB[arr_] + (size_t)(col0 + m_) * K + k0_ + c0);          \
        }                                                                       \
    }                                                                           \
} while (0)

    ISSUE(0, 0);
    cp_commit();

    for (int it = 0; it < niter; it++) {
        if (it + 1 < niter) {
            ISSUE(it + 1, (it + 1) & 1);
            cp_commit();
            asm volatile("cp.async.wait_group 1;\n" ::: "memory");
        } else {
            asm volatile("cp.async.wait_group 0;\n" ::: "memory");
        }
        __syncthreads();

        const uint32_t sst = sbase + (uint32_t)(it & 1) * (STG * 2);
#pragma unroll
        for (int ks = 0; ks < 2; ks++) {
            const int kofs = ks * 16;
            uint32_t ah[2][4], al[2][4], bh[4][4], bl[4][4];
#pragma unroll
            for (int mt = 0; mt < 2; mt++) {
                uint32_t addr = sst + (uint32_t)(((wm + mt*16 + a_row)*PAD + kofs + a_col) * 2);
                ldsm4(ah[mt], addr);
                ldsm4(al[mt], addr + ARR * 2);
            }
#pragma unroll
            for (int p = 0; p < 4; p++) {
                uint32_t addr = sst + (uint32_t)((2*ARR + (wn + p*16 + b_row)*PAD + kofs + b_col) * 2);
                ldsm4(bh[p], addr);
                ldsm4(bl[p], addr + ARR * 2);
            }
#pragma unroll
            for (int mt = 0; mt < 2; mt++)
#pragma unroll
                for (int p = 0; p < 4; p++) {
                    mma16816(acc[mt][2*p],   ah[mt], &bh[p][0]);
                    mma16816(acc[mt][2*p+1], ah[mt], &bh[p][2]);
                    mma16816(acc[mt][2*p],   ah[mt], &bl[p][0]);
                    mma16816(acc[mt][2*p+1], ah[mt], &bl[p][2]);
                    mma16816(acc[mt][2*p],   al[mt], &bh[p][0]);
                    mma16816(acc[mt][2*p+1], al[mt], &bh[p][2]);
                }
        }
        __syncthreads();
    }
#undef ISSUE

    const int gr = lane >> 2, gc = (lane & 3) * 2;
#pragma unroll
    for (int mt = 0; mt < 2; mt++)
#pragma unroll
        for (int nt = 0; nt < 8; nt++) {
            int row = row0 + wm + mt*16 + gr;
            int col = col0 + wn + nt*8 + gc;
            float2 v0 = make_float2(acc[mt][nt][0], acc[mt][nt][1]);
            float2 v1 = make_float2(acc[mt][nt][2], acc[mt][nt][3]);
            *(float2*)&C[(size_t)row*N + col]       = v0;
            *(float2*)&C[(size_t)(row+8)*N + col]   = v1;
        }
}

// ---------------- RMSNorm + RoPE -> bf16 hi/lo in [B,H,T,HD] ----------------
// scale_mul folds the softmax scale into Q (log2e/sqrt(HD)); 1.0 for K.
__global__ __launch_bounds__(128) void norm_rope_split_kernel(
    const float* __restrict__ raw, bf16* __restrict__ outh, bf16* __restrict__ outl,
    const float* __restrict__ scale,
    const float* __restrict__ cosT, const float* __restrict__ sinT,
    int H, float scale_mul)
{
    const int blk = blockIdx.x;
    const int h  = blk % H;
    const int bt = blk / H;
    const int t  = bt & (TT-1);
    const int b  = bt >> 11;
    const int d  = threadIdx.x;

    __shared__ float red[HD];
    float v = raw[(size_t)bt * (H*HD) + h*HD + d];
    red[d] = v*v;
    __syncthreads();
#pragma unroll
    for (int s = 64; s > 0; s >>= 1) {
        if (d < s) red[d] += red[d+s];
        __syncthreads();
    }
    float inv = rsqrtf(red[0]*(1.0f/HD) + 1e-6f);
    __syncthreads();
    float xn = v * inv * scale[d];
    red[d] = xn;
    __syncthreads();
    float rot = (d < 64) ? -red[d+64] : red[d-64];
    float o = (xn * cosT[t*HD + d] + rot * sinT[t*HD + d]) * scale_mul;
    size_t off = (((size_t)(b*H + h))*TT + t)*HD + d;
    bf16 hi = __float2bfloat16(o);
    outh[off] = hi;
    outl[off] = __float2bfloat16(o - __bfloat162float(hi));
}

// ---------------- fused flash attention (bf16x3 QK^T and PV) ----------------
// grid: (T/128 q-tiles, B*HQ). 256 threads = 8 warps, each warp owns 16 rows.
#define BQ 128
#define BK 64
#define FP 136
#define QELE (BQ*FP)        // 17408 bf16
#define KELE (BK*FP)        // 8704 bf16
#define QAREA (2*QELE)      // 34816
#define STGKV (4*KELE)      // 34816
#define FLASH_SMEM ((QAREA + 2*STGKV) * 2)   // 208896 bytes

__global__ __launch_bounds__(256) void flash_kernel(
    const bf16* __restrict__ Qh, const bf16* __restrict__ Ql,
    const bf16* __restrict__ Kh, const bf16* __restrict__ Kl,
    const bf16* __restrict__ Vh, const bf16* __restrict__ Vl,
    bf16* __restrict__ ctxh, bf16* __restrict__ ctxl)
{
    extern __shared__ bf16 sm[];
    const int tid = threadIdx.x, lane = tid & 31, wid = tid >> 5;
    const int qb = gridDim.x - 1 - blockIdx.x;     // longest tiles first
    const int bh = blockIdx.y;
    const int b = bh >> 4, h = bh & 15, kv = h >> 1;
    const int q0 = qb * BQ;
    const uint32_t sbase = (uint32_t)__cvta_generic_to_shared(sm);

    const bf16* Qhg = Qh + ((size_t)(b*HQ  + h )*TT + q0)*HD;
    const bf16* Qlg = Ql + ((size_t)(b*HQ  + h )*TT + q0)*HD;
    const bf16* Khg = Kh + ((size_t)(b*HKV + kv)*TT)*HD;
    const bf16* Klg = Kl + ((size_t)(b*HKV + kv)*TT)*HD;
    const bf16* Vhg = Vh + (size_t)b*TT*(HKV*HD) + kv*HD;
    const bf16* Vlg = Vl + (size_t)b*TT*(HKV*HD) + kv*HD;

    // ---- load Q (8 chunks per thread per array) ----
#pragma unroll
    for (int i = 0; i < 8; i++) {
        int c = tid + i*256;
        int row = c >> 4, col = (c & 15) * 8;
        cp_async16(sbase + (uint32_t)((row*FP + col) * 2),        Qhg + (size_t)row*HD + col);
        cp_async16(sbase + (uint32_t)((QELE + row*FP + col) * 2), Qlg + (size_t)row*HD + col);
    }

#define ISSUEKV(kt, stage) do {                                                     \
    const int k0_ = (kt) * BK;                                                      \
    const uint32_t kb_ = sbase + (uint32_t)((QAREA + (stage)*STGKV) * 2);           \
    _Pragma("unroll")                                                               \
    for (int i_ = 0; i_ < 4; i_++) {                                                \
        int c_ = tid + i_*256;                                                      \
        int row_ = c_ >> 4, col_ = (c_ & 15) * 8;                                   \
        uint32_t so_ = (uint32_t)((row_*FP + col_) * 2);                            \
        cp_async16(kb_ + so_,              Khg + (size_t)(k0_+row_)*HD + col_);     \
        cp_async16(kb_ + KELE*2 + so_,     Klg + (size_t)(k0_+row_)*HD + col_);     \
        cp_async16(kb_ + 2*KELE*2 + so_,   Vhg + (size_t)(k0_+row_)*(HKV*HD) + col_); \
        cp_async16(kb_ + 3*KELE*2 + so_,   Vlg + (size_t)(k0_+row_)*(HKV*HD) + col_); \
    }                                                                               \
} while (0)

    ISSUEKV(0, 0);
    cp_commit();

    const int r   = lane & 7, blkid = lane >> 3;
    const int a_row = ((blkid & 1) << 3) + r;
    const int a_col = (blkid >> 1) << 3;
    const int b_row = ((blkid >> 1) << 3) + r;
    const int b_col = (blkid & 1) << 3;
    const int gr = lane >> 2;

    float oacc[16][4];
#pragma unroll
    for (int i = 0; i < 16; i++)
#pragma unroll
        for (int j = 0; j < 4; j++) oacc[i][j] = 0.f;
    float m0 = -1e30f, m1 = -1e30f, l0 = 0.f, l1 = 0.f;

    const int row0g = q0 + wid*16 + gr;
    const int row1g = row0g + 8;
    const int nkt = 2*qb + 2;

    for (int kt = 0; kt < nkt; kt++) {
        if (kt + 1 < nkt) {
            ISSUEKV(kt + 1, (kt + 1) & 1);
            cp_commit();
            asm volatile("cp.async.wait_group 1;\n" ::: "memory");
        } else {
            asm volatile("cp.async.wait_group 0;\n" ::: "memory");
        }
        __syncthreads();

        const int k0 = kt * BK;
        const uint32_t kb_s = sbase + (uint32_t)((QAREA + (kt & 1)*STGKV) * 2);

        // ---- S = Q K^T (bf16x3) ----
        float sacc[8][4];
#pragma unroll
        for (int i = 0; i < 8; i++)
#pragma unroll
            for (int j = 0; j < 4; j++) sacc[i][j] = 0.f;

#pragma unroll
        for (int ks = 0; ks < 8; ks++) {
            uint32_t qa = sbase + (uint32_t)(((wid*16 + a_row)*FP + ks*16 + a_col) * 2);
            uint32_t qh[4], ql[4];
            ldsm4(qh, qa);
            ldsm4(ql, qa + QELE*2);
#pragma unroll
            for (int np = 0; np < 4; np++) {
                uint32_t ka = kb_s + (uint32_t)(((np*16 + b_row)*FP + ks*16 + b_col) * 2);
                uint32_t kh[4], kl[4];
                ldsm4(kh, ka);
                ldsm4(kl, ka + KELE*2);
                mma16816(sacc[2*np],   qh, &kh[0]);
                mma16816(sacc[2*np+1], qh, &kh[2]);
                mma16816(sacc[2*np],   qh, &kl[0]);
                mma16816(sacc[2*np+1], qh, &kl[2]);
                mma16816(sacc[2*np],   ql, &kh[0]);
                mma16816(sacc[2*np+1], ql, &kh[2]);
            }
        }

        // ---- causal mask + online softmax ----
        float mx0 = -1e30f, mx1 = -1e30f;
#pragma unroll
        for (int nt = 0; nt < 8; nt++) {
            int cg = k0 + nt*8 + (lane & 3)*2;
            if (cg     > row0g) sacc[nt][0] = -1e30f;
            if (cg + 1 > row0g) sacc[nt][1] = -1e30f;
            if (cg     > row1g) sacc[nt][2] = -1e30f;
            if (cg + 1 > row1g) sacc[nt][3] = -1e30f;
            mx0 = fmaxf(mx0, fmaxf(sacc[nt][0], sacc[nt][1]));
            mx1 = fmaxf(mx1, fmaxf(sacc[nt][2], sacc[nt][3]));
        }
        mx0 = fmaxf(mx0, __shfl_xor_sync(0xffffffffu, mx0, 1));
        mx0 = fmaxf(mx0, __shfl_xor_sync(0xffffffffu, mx0, 2));
        mx1 = fmaxf(mx1, __shfl_xor_sync(0xffffffffu, mx1, 1));
        mx1 = fmaxf(mx1, __shfl_xor_sync(0xffffffffu, mx1, 2));

        float mn0 = fmaxf(m0, mx0), mn1 = fmaxf(m1, mx1);
        float sc0 = exp2f(m0 - mn0), sc1 = exp2f(m1 - mn1);
        m0 = mn0; m1 = mn1;

        float s0 = 0.f, s1 = 0.f;
#pragma unroll
        for (int nt = 0; nt < 8; nt++) {
            sacc[nt][0] = exp2f(sacc[nt][0] - m0);
            sacc[nt][1] = exp2f(sacc[nt][1] - m0);
            sacc[nt][2] = exp2f(sacc[nt][2] - m1);
            sacc[nt][3] = exp2f(sacc[nt][3] - m1);
            s0 += sacc[nt][0] + sacc[nt][1];
            s1 += sacc[nt][2] + sacc[nt][3];
        }
        s0 += __shfl_xor_sync(0xffffffffu, s0, 1);
        s0 += __shfl_xor_sync(0xffffffffu, s0, 2);
        s1 += __shfl_xor_sync(0xffffffffu, s1, 1);
        s1 += __shfl_xor_sync(0xffffffffu, s1, 2);
        l0 = l0*sc0 + s0;
        l1 = l1*sc1 + s1;

#pragma unroll
        for (int i = 0; i < 16; i++) {
            oacc[i][0] *= sc0; oacc[i][1] *= sc0;
            oacc[i][2] *= sc1; oacc[i][3] *= sc1;
        }

        // ---- O += P V (bf16x3) ----
        const int vrow = (lane & 7) + ((lane >> 3) & 1)*8;
        const int vcolb = ((lane >> 4) << 3);
#pragma unroll
        for (int kp = 0; kp < 4; kp++) {
            uint32_t ph[4], pl[4];
#pragma unroll
            for (int half = 0; half < 2; half++) {
                float e0 = sacc[2*kp+half][0], e1 = sacc[2*kp+half][1];
                float e2 = sacc[2*kp+half][2], e3 = sacc[2*kp+half][3];
                bf16 b0 = __float2bfloat16(e0), b1 = __float2bfloat16(e1);
                bf16 b2 = __float2bfloat16(e2), b3 = __float2bfloat16(e3);
                ph[2*half]   = packbf(e0, e1);
                ph[2*half+1] = packbf(e2, e3);
                pl[2*half]   = packbf(e0 - __bfloat162float(b0), e1 - __bfloat162float(b1));
                pl[2*half+1] = packbf(e2 - __bfloat162float(b2), e3 - __bfloat162float(b3));
            }
#pragma unroll
            for (int np = 0; np < 8; np++) {
                uint32_t va = kb_s + (uint32_t)((2*KELE + (kp*16 + vrow)*FP + np*16 + vcolb) * 2);
                uint32_t vh[4], vl[4];
                ldsm4t(vh, va);
                ldsm4t(vl, va + KELE*2);
                mma16816(oacc[2*np],   ph, &vh[0]);
                mma16816(oacc[2*np+1], ph, &vh[2]);
                mma16816(oacc[2*np],   ph, &vl[0]);
                mma16816(oacc[2*np+1], ph, &vl[2]);
                mma16816(oacc[2*np],   pl, &vh[0]);
                mma16816(oacc[2*np+1], pl, &vh[2]);
            }
        }
        __syncthreads();
    }
#undef ISSUEKV

    // ---- epilogue: O /= l, write ctx hi/lo ----
    const float il0 = 1.f / l0, il1 = 1.f / l1;
    const size_t tok0 = (size_t)(b*TT + q0 + wid*16 + gr);
#pragma unroll
    for (int nt = 0; nt < 16; nt++) {
        int col = h*HD + nt*8 + (lane & 3)*2;
        float v0 = oacc[nt][0]*il0, v1 = oacc[nt][1]*il0;
        float v2 = oacc[nt][2]*il1, v3 = oacc[nt][3]*il1;
        bf16 h0 = __float2bfloat16(v0), h1 = __float2bfloat16(v1);
        bf16 h2 = __float2bfloat16(v2), h3 = __float2bfloat16(v3);
        *(uint32_t*)&ctxh[tok0*(HQ*HD) + col]     = packbf(v0, v1);
        *(uint32_t*)&ctxl[tok0*(HQ*HD) + col]     = packbf(v0 - __bfloat162float(h0), v1 - __bfloat162float(h1));
        *(uint32_t*)&ctxh[(tok0+8)*(HQ*HD) + col] = packbf(v2, v3);
        *(uint32_t*)&ctxl[(tok0+8)*(HQ*HD) + col] = packbf(v2 - __bfloat162float(h2), v3 - __bfloat162float(h3));
    }
}

// ---------------- launch ------------------------------------------------------
extern "C" void kernel_launch(void* const* d_in, const int* in_sizes, int n_in,
                              void* d_out, int out_size)
{
    const float* x       = (const float*)d_in[0];
    const float* cosT    = (const float*)d_in[2];
    const float* sinT    = (const float*)d_in[3];
    const float* Wq      = (const float*)d_in[4];
    const float* Wk      = (const float*)d_in[5];
    const float* Wv      = (const float*)d_in[6];
    const float* Wo      = (const float*)d_in[7];
    const float* q_scale = (const float*)d_in[8];
    const float* k_scale = (const float*)d_in[9];
    float* out = (float*)d_out;

    float *Qraw, *Kraw, *Vraw;
    bf16 *xh,*xl,*Wqh,*Wql,*Wkh,*Wkl,*Wvh,*Wvl,*Woh,*Wol;
    bf16 *Qh,*Ql,*Kh,*Kl,*Vh,*Vl,*ctxh,*ctxl;
    cudaGetSymbolAddress((void**)&Qraw, g_Qraw);
    cudaGetSymbolAddress((void**)&Kraw, g_Kraw);
    cudaGetSymbolAddress((void**)&Vraw, g_Vraw);
    cudaGetSymbolAddress((void**)&xh,   g_xh);   cudaGetSymbolAddress((void**)&xl,   g_xl);
    cudaGetSymbolAddress((void**)&Wqh,  g_Wqh);  cudaGetSymbolAddress((void**)&Wql,  g_Wql);
    cudaGetSymbolAddress((void**)&Wkh,  g_Wkh);  cudaGetSymbolAddress((void**)&Wkl,  g_Wkl);
    cudaGetSymbolAddress((void**)&Wvh,  g_Wvh);  cudaGetSymbolAddress((void**)&Wvl,  g_Wvl);
    cudaGetSymbolAddress((void**)&Woh,  g_Woh);  cudaGetSymbolAddress((void**)&Wol,  g_Wol);
    cudaGetSymbolAddress((void**)&Qh,   g_Qh);   cudaGetSymbolAddress((void**)&Ql,   g_Ql);
    cudaGetSymbolAddress((void**)&Kh,   g_Kh);   cudaGetSymbolAddress((void**)&Kl,   g_Kl);
    cudaGetSymbolAddress((void**)&Vh,   g_Vh);   cudaGetSymbolAddress((void**)&Vl,   g_Vl);
    cudaGetSymbolAddress((void**)&ctxh, g_ctxh); cudaGetSymbolAddress((void**)&ctxl, g_ctxl);

    static bool attr_set = false;
    if (!attr_set) {
        cudaFuncSetAttribute(gemm_bf16x3,  cudaFuncAttributeMaxDynamicSharedMemorySize, 2*STG*2);
        cudaFuncSetAttribute(flash_kernel, cudaFuncAttributeMaxDynamicSharedMemorySize, FLASH_SMEM);
        attr_set = true;
    }
    const int gsmem = 2*STG*2;

    // 0: split inputs/weights
    split_kernel<<<(MROWS*DD/4 + 255)/256, 256>>>((const float4*)x,  xh,  xl,  MROWS*DD/4);
    split_kernel<<<(HQ*HD*DD/4 + 255)/256, 256>>>((const float4*)Wq, Wqh, Wql, HQ*HD*DD/4);
    split_kernel<<<(HKV*HD*DD/4 + 255)/256, 256>>>((const float4*)Wk, Wkh, Wkl, HKV*HD*DD/4);
    split_kernel<<<(HKV*HD*DD/4 + 255)/256, 256>>>((const float4*)Wv, Wvh, Wvl, HKV*HD*DD/4);
    split_kernel<<<(DD*HQ*HD/4 + 255)/256, 256>>>((const float4*)Wo, Woh, Wol, DD*HQ*HD/4);

    // 1-3: QKV projections (tensor cores)
    gemm_bf16x3<<<dim3((HQ*HD)/128,  MROWS/128), 256, gsmem>>>(xh, xl, Wqh, Wql, Qraw, MROWS, HQ*HD,  DD);
    gemm_bf16x3<<<dim3((HKV*HD)/128, MROWS/128), 256, gsmem>>>(xh, xl, Wkh, Wkl, Kraw, MROWS, HKV*HD, DD);
    gemm_bf16x3<<<dim3((HKV*HD)/128, MROWS/128), 256, gsmem>>>(xh, xl, Wvh, Wvl, Vraw, MROWS, HKV*HD, DD);

    // 4-6: norm+rope -> bf16 hi/lo; V split
    norm_rope_split_kernel<<<MROWS*HQ,  128>>>(Qraw, Qh, Ql, q_scale, cosT, sinT, HQ,  QSCALE);
    norm_rope_split_kernel<<<MROWS*HKV, 128>>>(Kraw, Kh, Kl, k_scale, cosT, sinT, HKV, 1.0f);
    split_kernel<<<(MROWS*HKV*HD/4 + 255)/256, 256>>>((const float4*)Vraw, Vh, Vl, MROWS*HKV*HD/4);

    // 7: fused flash attention
    flash_kernel<<<dim3(TT/BQ, BB*HQ), 256, FLASH_SMEM>>>(Qh, Ql, Kh, Kl, Vh, Vl, ctxh, ctxl);

    // 8: output projection (tensor cores)
    gemm_bf16x3<<<dim3(DD/128, MROWS/128), 256, gsmem>>>(ctxh, ctxl, Woh, Wol, out, MROWS, DD, DD);
}